// round 4
// baseline (speedup 1.0000x reference)
#include <cuda_runtime.h>
#include <math.h>

// ---------------- problem constants ----------------
#define B_  8
#define N_  2048
#define D_  16
#define K_  8
#define H_  4
#define HD_ 8
#define SCALE_ 0.35355339059327373f   // hd^-0.5

typedef unsigned long long ull;

// ---------------- packed f32x2 helpers ----------------
#define FMA2(d, a, b, c) asm("fma.rn.f32x2 %0, %1, %2, %3;" : "=l"(d) : "l"(a), "l"(b), "l"(c))
__device__ __forceinline__ ull pack2(float lo, float hi) {
    ull r; asm("mov.b64 %0, {%1, %2};" : "=l"(r) : "f"(lo), "f"(hi)); return r;
}
__device__ __forceinline__ void unpack2(ull v, float& lo, float& hi) {
    asm("mov.b64 {%0, %1}, %2;" : "=f"(lo), "=f"(hi) : "l"(v));
}

// ---------------- scratch ----------------
__device__ float g_Q   [B_ * N_ * 32];
__device__ float g_Kt  [B_ * N_ * 32];
__device__ float g_att [B_ * N_ * D_];
__device__ float g_cand[(size_t)B_ * K_ * N_ * D_];
__device__ float g_wsumAcc[B_ * D_];
__device__ float g_hypf[B_ * K_ * D_];
__device__ float g_fimraw[B_ * K_];
__device__ float g_w   [B_ * K_];
__device__ float g_mod [B_ * D_];

// ---------------- Cl(3,0,1) helpers ----------------
__device__ __forceinline__ float cayley_sign(int a, int b) {
    int neg = 0;
#pragma unroll
    for (int i = 0; i < 4; i++)
        if ((b >> i) & 1) neg ^= (__popc(a >> (i + 1)) & 1);
    if ((a & b) & 8) return 0.f;
    return neg ? -1.f : 1.f;
}
__device__ __forceinline__ float rev_sign(int i) {
    int p = __popc(i);
    return ((p * (p - 1) / 2) & 1) ? -1.f : 1.f;
}

__device__ __forceinline__ float fast_tanh(float x) {
    float ex = __expf(2.f * x);
    return 1.f - __fdividef(2.f, ex + 1.f);
}

// ---------------- kernel 1: Q/K projection (+ init of accumulators) ----------------
__global__ __launch_bounds__(128) void proj_kernel(const float* __restrict__ state,
                            const float* __restrict__ Wq, const float* __restrict__ bq,
                            const float* __restrict__ Wk, const float* __restrict__ bk,
                            const float* __restrict__ hyp,
                            const float* __restrict__ W_hyp,
                            const float* __restrict__ b_hyp) {
    __shared__ float sWq[16][32], sWk[16][32], sbq[32], sbk[32];
    int t = threadIdx.x;
    if (blockIdx.x == 0) {
        if (t < B_ * K_) g_fimraw[t] = 0.f;
        if (t < B_ * D_) g_wsumAcc[t] = 0.f;
        for (int i = t; i < B_ * K_ * D_; i += 128) {
            int bk_ = i >> 4, d = i & 15;
            float v = b_hyp[d];
#pragma unroll
            for (int c = 0; c < 4; c++) v = fmaf(hyp[bk_ * 4 + c], W_hyp[c * D_ + d], v);
            g_hypf[i] = v;
        }
    }
    for (int i = t; i < 512; i += 128) { sWq[i >> 5][i & 31] = Wq[i]; sWk[i >> 5][i & 31] = Wk[i]; }
    if (t < 32) { sbq[t] = bq[t]; sbk[t] = bk[t]; }
    __syncthreads();
    size_t row = (size_t)blockIdx.x * 128 + t;
    float s[16];
    const float4* sp = (const float4*)(state + row * 16);
#pragma unroll
    for (int i = 0; i < 4; i++) { float4 v = sp[i]; s[4*i]=v.x; s[4*i+1]=v.y; s[4*i+2]=v.z; s[4*i+3]=v.w; }
    ull sd[16];
#pragma unroll
    for (int d = 0; d < 16; d++) sd[d] = pack2(s[d], s[d]);
    ull* qo = (ull*)(g_Q  + row * 32);
    ull* ko = (ull*)(g_Kt + row * 32);
#pragma unroll
    for (int c2 = 0; c2 < 16; c2++) {
        ull aq = ((const ull*)sbq)[c2];
        ull ak = ((const ull*)sbk)[c2];
#pragma unroll
        for (int d = 0; d < 16; d++) {
            FMA2(aq, sd[d], ((const ull*)&sWq[d][0])[c2], aq);
            FMA2(ak, sd[d], ((const ull*)&sWk[d][0])[c2], ak);
        }
        qo[c2] = aq; ko[c2] = ak;
    }
}

// ---------------- kernel 2: fused attention (64 rows/block, 128 thr) ----------------
#define TM_ 128
__global__ __launch_bounds__(128) void attn_kernel(const float* __restrict__ state,
                                                   const float* __restrict__ v_gains) {
    int b    = blockIdx.y;
    int t    = threadIdx.x;
    int head = t & 3;
    int g    = t >> 2;                         // 0..31
    int n0   = blockIdx.x * 64 + g * 2;

    __shared__ float Ks[TM_][32];
    __shared__ float Ss[TM_][16];
    __shared__ float sW[4][16];

    ull q[2][4];
#pragma unroll
    for (int r = 0; r < 2; r++) {
        const float4* qp = (const float4*)(g_Q + ((size_t)b * N_ + n0 + r) * 32 + head * 8);
        float4 a = qp[0], c = qp[1];
        q[r][0] = pack2(a.x * SCALE_, a.y * SCALE_);
        q[r][1] = pack2(a.z * SCALE_, a.w * SCALE_);
        q[r][2] = pack2(c.x * SCALE_, c.y * SCALE_);
        q[r][3] = pack2(c.z * SCALE_, c.w * SCALE_);
    }
    ull o[2][8];
#pragma unroll
    for (int r = 0; r < 2; r++)
#pragma unroll
        for (int j = 0; j < 8; j++) o[r][j] = 0ULL;
    float l0 = 0.f, l1 = 0.f;

    for (int m0 = 0; m0 < N_; m0 += TM_) {
        __syncthreads();
#pragma unroll
        for (int i = 0; i < 8; i++) {
            int idx = t + i * 128;             // Ks: 1024 float4
            int r = idx >> 3, c = idx & 7;
            ((float4*)&Ks[r][0])[c] = ((const float4*)(g_Kt + ((size_t)b * N_ + m0 + r) * 32))[c];
        }
#pragma unroll
        for (int i = 0; i < 4; i++) {
            int idx = t + i * 128;             // Ss: 512 float4
            int r = idx >> 2, c = idx & 3;
            ((float4*)&Ss[r][0])[c] = ((const float4*)(state + ((size_t)b * N_ + m0 + r) * 16))[c];
        }
        __syncthreads();
#pragma unroll 4
        for (int mm = 0; mm < TM_; mm++) {
            const ulonglong2* kp = (const ulonglong2*)&Ks[mm][head * 8];
            ulonglong2 ka = kp[0], kb = kp[1];
            const ulonglong2* vp = (const ulonglong2*)&Ss[mm][0];
            ulonglong2 va = vp[0], vb = vp[1], vc = vp[2], vd = vp[3];
#pragma unroll
            for (int r = 0; r < 2; r++) {
                ull acc;
                FMA2(acc, q[r][0], ka.x, 0ULL);
                FMA2(acc, q[r][1], ka.y, acc);
                FMA2(acc, q[r][2], kb.x, acc);
                FMA2(acc, q[r][3], kb.y, acc);
                float lo, hi; unpack2(acc, lo, hi);
                float s = fminf(lo + hi, 60.f);
                float p = __expf(s);
                if (r == 0) l0 += p; else l1 += p;
                ull pp = pack2(p, p);
                FMA2(o[r][0], pp, va.x, o[r][0]);
                FMA2(o[r][1], pp, va.y, o[r][1]);
                FMA2(o[r][2], pp, vb.x, o[r][2]);
                FMA2(o[r][3], pp, vb.y, o[r][3]);
                FMA2(o[r][4], pp, vc.x, o[r][4]);
                FMA2(o[r][5], pp, vc.y, o[r][5]);
                FMA2(o[r][6], pp, vd.x, o[r][6]);
                FMA2(o[r][7], pp, vd.y, o[r][7]);
            }
        }
    }

    // epilogue: per-row head combine + write + world-summary partials
    float gain = 0.25f * v_gains[0];
    float wacc[16];
#pragma unroll
    for (int d = 0; d < 16; d++) wacc[d] = 0.f;
#pragma unroll
    for (int r = 0; r < 2; r++) {
        float inv = 1.f / (r == 0 ? l0 : l1);
        float ov[16];
#pragma unroll
        for (int j = 0; j < 8; j++) unpack2(o[r][j], ov[2*j], ov[2*j+1]);
#pragma unroll
        for (int d = 0; d < 16; d++) {
            float v = ov[d] * inv;
            v += __shfl_xor_sync(0xffffffffu, v, 1);
            v += __shfl_xor_sync(0xffffffffu, v, 2);
            v *= gain;
            ov[d] = v;
            wacc[d] += v;
        }
        if (head == 0) {
            float4* ap = (float4*)(g_att + ((size_t)b * N_ + n0 + r) * 16);
#pragma unroll
            for (int i = 0; i < 4; i++)
                ap[i] = make_float4(ov[4*i], ov[4*i+1], ov[4*i+2], ov[4*i+3]);
        }
    }
    // reduce across the 8 quads of the warp; each quad contributes once.
#pragma unroll
    for (int d = 0; d < 16; d++) {
        float v = wacc[d];
        v += __shfl_xor_sync(0xffffffffu, v, 4);
        v += __shfl_xor_sync(0xffffffffu, v, 8);
        v += __shfl_xor_sync(0xffffffffu, v, 16);
        wacc[d] = v;
    }
    if ((t & 31) == 0) {
#pragma unroll
        for (int d = 0; d < 16; d++) sW[t >> 5][d] = wacc[d];
    }
    __syncthreads();
    if (t < 16) {
        float s = sW[0][t] + sW[1][t] + sW[2][t] + sW[3][t];
        atomicAdd(&g_wsumAcc[b * 16 + t], s);
    }
}

// ---------------- kernel 3: candidates + fim partials ----------------
__global__ __launch_bounds__(256) void cand_kernel(const float* __restrict__ W_act,
                            const float* __restrict__ b_act) {
    int b = blockIdx.z, k = blockIdx.y, ch = blockIdx.x;
    __shared__ float W[16][16];
    __shared__ float bias[16];
    int t = threadIdx.x;
    W[t >> 4][t & 15] = W_act[(k * 16 + (t >> 4)) * 16 + (t & 15)];
    if (t < 16) bias[t] = b_act[k * 16 + t] + g_hypf[(b * K_ + k) * 16 + t];
    __syncthreads();
    int n = ch * 256 + t;
    float a[16];
    const float4* ap = (const float4*)(g_att + ((size_t)b * N_ + n) * 16);
#pragma unroll
    for (int i = 0; i < 4; i++) { float4 v = ap[i]; a[4*i]=v.x; a[4*i+1]=v.y; a[4*i+2]=v.z; a[4*i+3]=v.w; }
    ull ad[16];
#pragma unroll
    for (int d = 0; d < 16; d++) ad[d] = pack2(a[d], a[d]);
    float c[16], ss = 0.f;
#pragma unroll
    for (int e2 = 0; e2 < 8; e2++) {
        ull acc = ((const ull*)bias)[e2];
#pragma unroll
        for (int d = 0; d < 16; d++) FMA2(acc, ad[d], ((const ull*)&W[d][0])[e2], acc);
        float v0, v1; unpack2(acc, v0, v1);
        v0 = fast_tanh(v0); v1 = fast_tanh(v1);
        c[2*e2] = v0; c[2*e2+1] = v1;
        ss = fmaf(v0, v0, fmaf(v1, v1, ss));
    }
    float4* cp = (float4*)(g_cand + (((size_t)(b * K_ + k)) * N_ + n) * 16);
#pragma unroll
    for (int i = 0; i < 4; i++) cp[i] = make_float4(c[4*i], c[4*i+1], c[4*i+2], c[4*i+3]);
    ss *= (1.f / 16.f);
#pragma unroll
    for (int off = 16; off > 0; off >>= 1) ss += __shfl_xor_sync(0xffffffffu, ss, off);
    __shared__ float wsums[8];
    if ((t & 31) == 0) wsums[t >> 5] = ss;
    __syncthreads();
    if (t == 0) {
        float tot = 0.f;
#pragma unroll
        for (int i = 0; i < 8; i++) tot += wsums[i];
        atomicAdd(&g_fimraw[b * K_ + k], tot);
    }
}

// ---------------- kernel 4: tiny math (parallelized) ----------------
__global__ __launch_bounds__(256) void small_kernel(const float* __restrict__ hyp,
                             const float* __restrict__ R_accum,
                             const float* __restrict__ W_ws, const float* __restrict__ b_ws,
                             const float* __restrict__ W_s1, const float* __restrict__ b_s1,
                             const float* __restrict__ W_s2, const float* __restrict__ b_s2,
                             const float* __restrict__ W_lift, const float* __restrict__ b_lift,
                             const float* __restrict__ rotors,
                             float* __restrict__ out_newhyp, float* __restrict__ out_R,
                             float* __restrict__ out_fim, float* __restrict__ out_w) {
    int t = threadIdx.x;
    __shared__ float sW1[640];      // W_s1 [10,64]
    __shared__ float sW2[320];      // W_s2 [64,5]
    __shared__ float sb1[64];
    __shared__ float sb2v[5];
    __shared__ float s_logit[64];
    __shared__ float s_nh[64][4];
    for (int i = t; i < 640; i += 256) sW1[i] = W_s1[i];
    for (int i = t; i < 320; i += 256) sW2[i] = W_s2[i];
    if (t < 64) sb1[t] = b_s1[t];
    if (t < 5)  sb2v[t] = b_s2[t];
    __syncthreads();

    int p = t >> 2;                 // (b,k) pair 0..63
    int q = t & 3;                  // j-chunk
    int b = p >> 3;
    float fim = g_fimraw[p] * (1.f / (float)N_);
    float feat[10];
#pragma unroll
    for (int c = 0; c < 4; c++) feat[c] = hyp[p * 4 + c];
#pragma unroll
    for (int c = 0; c < 4; c++) {
        float v = b_ws[c];
#pragma unroll
        for (int d = 0; d < 16; d++)
            v = fmaf(g_wsumAcc[b * 16 + d] * (1.f / (float)N_), W_ws[d * 4 + c], v);
        feat[4 + c] = v;
    }
    feat[8] = fim; feat[9] = fim;
    float sp[5] = {0.f, 0.f, 0.f, 0.f, 0.f};
    for (int j = q; j < 64; j += 4) {
        float h = sb1[j];
#pragma unroll
        for (int i = 0; i < 10; i++) h = fmaf(feat[i], sW1[i * 64 + j], h);
        h = fmaxf(h, 0.f);
#pragma unroll
        for (int c = 0; c < 5; c++) sp[c] = fmaf(h, sW2[j * 5 + c], sp[c]);
    }
#pragma unroll
    for (int c = 0; c < 5; c++) {
        sp[c] += __shfl_xor_sync(0xffffffffu, sp[c], 1);
        sp[c] += __shfl_xor_sync(0xffffffffu, sp[c], 2);
    }
    if (q == 0) {
        out_fim[p] = fim;
#pragma unroll
        for (int c = 0; c < 4; c++) {
            float nh = hyp[p * 4 + c] + sp[c] + sb2v[c];
            s_nh[p][c] = nh;
            out_newhyp[p * 4 + c] = nh;
        }
        s_logit[p] = sp[4] + sb2v[4];
    }
    __syncthreads();
    if (t < 8) {
        int bb_ = t;
        float mx = -1e30f;
#pragma unroll
        for (int k = 0; k < 8; k++) mx = fmaxf(mx, s_logit[bb_ * 8 + k]);
        float e[8], se = 0.f;
#pragma unroll
        for (int k = 0; k < 8; k++) { e[k] = __expf(s_logit[bb_ * 8 + k] - mx); se += e[k]; }
        float w[8], inv = 1.f / se;
#pragma unroll
        for (int k = 0; k < 8; k++) {
            w[k] = e[k] * inv;
            out_w[bb_ * 8 + k] = w[k];
            g_w[bb_ * 8 + k] = w[k];
        }
        float agg[4] = {0.f, 0.f, 0.f, 0.f};
#pragma unroll
        for (int k = 0; k < 8; k++)
#pragma unroll
            for (int c = 0; c < 4; c++) agg[c] = fmaf(w[k], s_nh[bb_ * 8 + k][c], agg[c]);
#pragma unroll
        for (int d = 0; d < 16; d++) {
            float v = b_lift[d];
#pragma unroll
            for (int c = 0; c < 4; c++) v = fmaf(agg[c], W_lift[c * 16 + d], v);
            g_mod[bb_ * 16 + d] = 1.f + tanhf(v);
        }
        float Rt[16];
#pragma unroll
        for (int d = 0; d < 16; d++) {
            float v = 0.f;
#pragma unroll
            for (int k = 0; k < 8; k++) v = fmaf(w[k], rotors[k * 16 + d], v);
            Rt[d] = v;
        }
        float Rn[16];
#pragma unroll
        for (int d = 0; d < 16; d++) Rn[d] = 0.f;
        for (int a = 0; a < 16; a++) {
            float xa = Rt[a];
            for (int bb = 0; bb < 16; bb++) {
                float s = cayley_sign(a, bb);
                if (s != 0.f) Rn[a ^ bb] = fmaf(s * xa, R_accum[bb_ * 16 + bb], Rn[a ^ bb]);
            }
        }
        float g0 = 0.f;
        for (int a = 0; a < 16; a++) {
            float s = cayley_sign(a, a);
            g0 += s * Rn[a] * Rn[a] * rev_sign(a);
        }
        g0 = fmaxf(fabsf(g0), 1e-6f);
        float rinv = rsqrtf(g0);
#pragma unroll
        for (int d = 0; d < 16; d++) out_R[bb_ * 16 + d] = Rn[d] * rinv;
    }
}

// ---------------- kernel 5: weighted select + gates + norm ----------------
__global__ __launch_bounds__(128) void final_kernel(const float* __restrict__ state,
                            const float* __restrict__ Wg1, const float* __restrict__ bg1,
                            const float* __restrict__ Wg2, const float* __restrict__ bg2,
                            const float* __restrict__ Wc1, const float* __restrict__ bc1,
                            const float* __restrict__ Wc2, const float* __restrict__ bc2,
                            const float* __restrict__ norm_scale,
                            float* __restrict__ out_ns, float* __restrict__ out_gate) {
    int b = blockIdx.y;
    int n = blockIdx.x * 128 + threadIdx.x;
    __shared__ float sWg1[32][64];
    __shared__ float sWg2[64][16];
    __shared__ float sbg1[64], sbg2[16], sWc1[2][16], sbc1[16], sWc2[16], sns[16];
    __shared__ float sw[8], smod[16], sbc2;
    int t = threadIdx.x;
    for (int i = t; i < 2048; i += 128) sWg1[i >> 6][i & 63] = Wg1[i];
    for (int i = t; i < 1024; i += 128) sWg2[i >> 4][i & 15] = Wg2[i];
    if (t < 64) sbg1[t] = bg1[t];
    if (t < 16) { sbg2[t] = bg2[t]; sbc1[t] = bc1[t]; sWc2[t] = Wc2[t]; sns[t] = norm_scale[t];
                  smod[t] = g_mod[b * 16 + t]; }
    if (t < 32) sWc1[t >> 4][t & 15] = Wc1[t];
    if (t < 8)  sw[t] = g_w[b * 8 + t];
    if (t == 0) sbc2 = bc2[0];
    __syncthreads();

    float in[32];
    const float4* sp = (const float4*)(state + ((size_t)b * N_ + n) * 16);
#pragma unroll
    for (int i = 0; i < 4; i++) { float4 v = sp[i]; in[4*i]=v.x; in[4*i+1]=v.y; in[4*i+2]=v.z; in[4*i+3]=v.w; }

    float ns_[16];
#pragma unroll
    for (int e = 0; e < 16; e++) ns_[e] = 0.f;
#pragma unroll
    for (int k = 0; k < 8; k++) {
        const float4* cp = (const float4*)(g_cand + (((size_t)(b * K_ + k)) * N_ + n) * 16);
        float wk = sw[k];
#pragma unroll
        for (int i = 0; i < 4; i++) {
            float4 v = cp[i];
            ns_[4*i]   = fmaf(wk, v.x, ns_[4*i]);
            ns_[4*i+1] = fmaf(wk, v.y, ns_[4*i+1]);
            ns_[4*i+2] = fmaf(wk, v.z, ns_[4*i+2]);
            ns_[4*i+3] = fmaf(wk, v.w, ns_[4*i+3]);
        }
    }
#pragma unroll
    for (int e = 0; e < 16; e++) { ns_[e] *= smod[e]; in[16 + e] = ns_[e]; }

    ull accE[8];
#pragma unroll
    for (int e2 = 0; e2 < 8; e2++) accE[e2] = ((const ull*)sbg2)[e2];
#pragma unroll
    for (int half = 0; half < 2; half++) {
        ull accH[16];
#pragma unroll
        for (int j2 = 0; j2 < 16; j2++) accH[j2] = ((const ull*)sbg1)[half * 16 + j2];
#pragma unroll
        for (int i = 0; i < 32; i++) {
            ull ind = pack2(in[i], in[i]);
            const ull* wrow = (const ull*)&sWg1[i][half * 32];
#pragma unroll
            for (int j2 = 0; j2 < 16; j2++) FMA2(accH[j2], ind, wrow[j2], accH[j2]);
        }
#pragma unroll
        for (int j2 = 0; j2 < 16; j2++) {
            float h0, h1; unpack2(accH[j2], h0, h1);
            h0 = fmaxf(h0, 0.f); h1 = fmaxf(h1, 0.f);
            int j = half * 32 + j2 * 2;
            ull hd0 = pack2(h0, h0), hd1 = pack2(h1, h1);
            const ull* w0 = (const ull*)&sWg2[j][0];
            const ull* w1 = (const ull*)&sWg2[j + 1][0];
#pragma unroll
            for (int e2 = 0; e2 < 8; e2++) {
                FMA2(accE[e2], hd0, w0[e2], accE[e2]);
                FMA2(accE[e2], hd1, w1[e2], accE[e2]);
            }
        }
    }
    float gate[16];
#pragma unroll
    for (int e2 = 0; e2 < 8; e2++) {
        float a0, a1; unpack2(accE[e2], a0, a1);
        gate[2*e2]   = 1.f / (1.f + __expf(-a0));
        gate[2*e2+1] = 1.f / (1.f + __expf(-a1));
    }

    float cg = sbc2;
#pragma unroll
    for (int j = 0; j < 16; j++) {
        float h = fmaf(in[0], sWc1[0][j], fmaf(ns_[0], sWc1[1][j], sbc1[j]));
        h = fmaxf(h, 0.f);
        cg = fmaf(h, sWc2[j], cg);
    }
    cg = 1.f / (1.f + __expf(-cg));

    float val[16];
    val[0] = cg * ns_[0] + (1.f - cg) * in[0];
#pragma unroll
    for (int d = 1; d < 16; d++) val[d] = gate[d] * ns_[d] + (1.f - gate[d]) * in[d];

    float ms = 0.f;
#pragma unroll
    for (int d = 0; d < 16; d++) ms = fmaf(val[d], val[d], ms);
    float r = rsqrtf(ms * (1.f / 16.f) + 1e-6f);

    float4* no = (float4*)(out_ns + ((size_t)b * N_ + n) * 16);
    float4* go = (float4*)(out_gate + ((size_t)b * N_ + n) * 16);
#pragma unroll
    for (int i = 0; i < 4; i++) {
        no[i] = make_float4(val[4*i] * sns[4*i] * r, val[4*i+1] * sns[4*i+1] * r,
                            val[4*i+2] * sns[4*i+2] * r, val[4*i+3] * sns[4*i+3] * r);
        go[i] = make_float4(gate[4*i], gate[4*i+1], gate[4*i+2], gate[4*i+3]);
    }
}

// ---------------- launch ----------------
extern "C" void kernel_launch(void* const* d_in, const int* in_sizes, int n_in,
                              void* d_out, int out_size) {
    const float* state   = (const float*)d_in[0];
    const float* hyp     = (const float*)d_in[1];
    const float* R_accum = (const float*)d_in[2];
    const float* Wq = (const float*)d_in[4];
    const float* bq = (const float*)d_in[5];
    const float* Wk = (const float*)d_in[6];
    const float* bk = (const float*)d_in[7];
    const float* v_gains = (const float*)d_in[8];
    const float* W_act = (const float*)d_in[9];
    const float* b_act = (const float*)d_in[10];
    const float* W_hyp = (const float*)d_in[11];
    const float* b_hyp = (const float*)d_in[12];
    const float* W_ws = (const float*)d_in[13];
    const float* b_ws = (const float*)d_in[14];
    const float* W_s1 = (const float*)d_in[15];
    const float* b_s1 = (const float*)d_in[16];
    const float* W_s2 = (const float*)d_in[17];
    const float* b_s2 = (const float*)d_in[18];
    const float* W_lift = (const float*)d_in[19];
    const float* b_lift = (const float*)d_in[20];
    const float* Wg1 = (const float*)d_in[21];
    const float* bg1 = (const float*)d_in[22];
    const float* Wg2 = (const float*)d_in[23];
    const float* bg2 = (const float*)d_in[24];
    const float* Wc1 = (const float*)d_in[25];
    const float* bc1 = (const float*)d_in[26];
    const float* Wc2 = (const float*)d_in[27];
    const float* bc2 = (const float*)d_in[28];
    const float* norm_scale = (const float*)d_in[29];
    const float* rotors = (const float*)d_in[30];

    float* out = (float*)d_out;
    float* out_ns     = out;
    float* out_newhyp = out + (size_t)B_ * N_ * D_;
    float* out_R      = out_newhyp + B_ * K_ * 4;
    float* out_fim    = out_R + B_ * 16;
    float* out_w      = out_fim + B_ * K_;
    float* out_gate   = out_w + B_ * K_;

    proj_kernel<<<(B_ * N_) / 128, 128>>>(state, Wq, bq, Wk, bk, hyp, W_hyp, b_hyp);
    attn_kernel<<<dim3(N_ / 64, B_), 128>>>(state, v_gains);
    cand_kernel<<<dim3(N_ / 256, K_, B_), 256>>>(W_act, b_act);
    small_kernel<<<1, 256>>>(hyp, R_accum, W_ws, b_ws, W_s1, b_s1, W_s2, b_s2,
                             W_lift, b_lift, rotors,
                             out_newhyp, out_R, out_fim, out_w);
    final_kernel<<<dim3(N_ / 128, B_), 128>>>(state, Wg1, bg1, Wg2, bg2,
                                              Wc1, bc1, Wc2, bc2, norm_scale,
                                              out_ns, out_gate);
}

// round 5
// speedup vs baseline: 1.2277x; 1.2277x over previous
#include <cuda_runtime.h>
#include <math.h>

// ---------------- problem constants ----------------
#define B_  8
#define N_  2048
#define D_  16
#define K_  8
#define H_  4
#define HD_ 8
#define SCALE_ 0.35355339059327373f   // hd^-0.5

typedef unsigned long long ull;

// ---------------- packed f32x2 helpers ----------------
#define FMA2(d, a, b, c) asm("fma.rn.f32x2 %0, %1, %2, %3;" : "=l"(d) : "l"(a), "l"(b), "l"(c))
__device__ __forceinline__ ull pack2(float lo, float hi) {
    ull r; asm("mov.b64 %0, {%1, %2};" : "=l"(r) : "f"(lo), "f"(hi)); return r;
}
__device__ __forceinline__ void unpack2(ull v, float& lo, float& hi) {
    asm("mov.b64 {%0, %1}, %2;" : "=f"(lo), "=f"(hi) : "l"(v));
}

// ---------------- scratch ----------------
__device__ float g_Q   [B_ * N_ * 32];
__device__ float g_Kt  [B_ * N_ * 32];
__device__ float g_att [B_ * N_ * D_];
__device__ float g_cand[(size_t)B_ * K_ * N_ * D_];
__device__ float g_wsumAcc[B_ * D_];
__device__ float g_hypf[B_ * K_ * D_];
__device__ float g_fimraw[B_ * K_];

// ---------------- Cl(3,0,1) helpers ----------------
__device__ __forceinline__ float cayley_sign(int a, int b) {
    int neg = 0;
#pragma unroll
    for (int i = 0; i < 4; i++)
        if ((b >> i) & 1) neg ^= (__popc(a >> (i + 1)) & 1);
    if ((a & b) & 8) return 0.f;
    return neg ? -1.f : 1.f;
}
__device__ __forceinline__ float rev_sign(int i) {
    int p = __popc(i);
    return ((p * (p - 1) / 2) & 1) ? -1.f : 1.f;
}

__device__ __forceinline__ float fast_tanh(float x) {
    float ex = __expf(2.f * x);
    return 1.f - __fdividef(2.f, ex + 1.f);
}

// ---------------- kernel 1: Q/K projection (+ init of accumulators) ----------------
__global__ __launch_bounds__(128) void proj_kernel(const float* __restrict__ state,
                            const float* __restrict__ Wq, const float* __restrict__ bq,
                            const float* __restrict__ Wk, const float* __restrict__ bk,
                            const float* __restrict__ hyp,
                            const float* __restrict__ W_hyp,
                            const float* __restrict__ b_hyp) {
    __shared__ float sWq[16][32], sWk[16][32], sbq[32], sbk[32];
    int t = threadIdx.x;
    if (blockIdx.x == 0) {
        if (t < B_ * K_) g_fimraw[t] = 0.f;
        if (t < B_ * D_) g_wsumAcc[t] = 0.f;
        for (int i = t; i < B_ * K_ * D_; i += 128) {
            int bk_ = i >> 4, d = i & 15;
            float v = b_hyp[d];
#pragma unroll
            for (int c = 0; c < 4; c++) v = fmaf(hyp[bk_ * 4 + c], W_hyp[c * D_ + d], v);
            g_hypf[i] = v;
        }
    }
    for (int i = t; i < 512; i += 128) { sWq[i >> 5][i & 31] = Wq[i]; sWk[i >> 5][i & 31] = Wk[i]; }
    if (t < 32) { sbq[t] = bq[t]; sbk[t] = bk[t]; }
    __syncthreads();
    size_t row = (size_t)blockIdx.x * 128 + t;
    float s[16];
    const float4* sp = (const float4*)(state + row * 16);
#pragma unroll
    for (int i = 0; i < 4; i++) { float4 v = sp[i]; s[4*i]=v.x; s[4*i+1]=v.y; s[4*i+2]=v.z; s[4*i+3]=v.w; }
    ull sd[16];
#pragma unroll
    for (int d = 0; d < 16; d++) sd[d] = pack2(s[d], s[d]);
    ull* qo = (ull*)(g_Q  + row * 32);
    ull* ko = (ull*)(g_Kt + row * 32);
#pragma unroll
    for (int c2 = 0; c2 < 16; c2++) {
        ull aq = ((const ull*)sbq)[c2];
        ull ak = ((const ull*)sbk)[c2];
#pragma unroll
        for (int d = 0; d < 16; d++) {
            FMA2(aq, sd[d], ((const ull*)&sWq[d][0])[c2], aq);
            FMA2(ak, sd[d], ((const ull*)&sWk[d][0])[c2], ak);
        }
        qo[c2] = aq; ko[c2] = ak;
    }
}

// ---------------- kernel 2: fused attention (R3 geometry: 128 rows/block, 256 thr) ----------------
#define TM_ 128
__global__ __launch_bounds__(256, 1) void attn_kernel(const float* __restrict__ state,
                                                      const float* __restrict__ v_gains) {
    int b    = blockIdx.y;
    int t    = threadIdx.x;
    int head = t & 3;
    int g    = t >> 2;                         // 0..63
    int n0   = blockIdx.x * 128 + g * 2;

    __shared__ float Ks[TM_][32];
    __shared__ float Ss[TM_][16];
    __shared__ float sW[8][16];

    ull q[2][4];
#pragma unroll
    for (int r = 0; r < 2; r++) {
        const float4* qp = (const float4*)(g_Q + ((size_t)b * N_ + n0 + r) * 32 + head * 8);
        float4 a = qp[0], c = qp[1];
        q[r][0] = pack2(a.x * SCALE_, a.y * SCALE_);
        q[r][1] = pack2(a.z * SCALE_, a.w * SCALE_);
        q[r][2] = pack2(c.x * SCALE_, c.y * SCALE_);
        q[r][3] = pack2(c.z * SCALE_, c.w * SCALE_);
    }
    ull o[2][8];
#pragma unroll
    for (int r = 0; r < 2; r++)
#pragma unroll
        for (int j = 0; j < 8; j++) o[r][j] = 0ULL;
    float l0 = 0.f, l1 = 0.f;

    for (int m0 = 0; m0 < N_; m0 += TM_) {
        __syncthreads();
#pragma unroll
        for (int i = 0; i < 4; i++) {
            int idx = t + i * 256;             // Ks: 1024 float4
            int r = idx >> 3, c = idx & 7;
            ((float4*)&Ks[r][0])[c] = ((const float4*)(g_Kt + ((size_t)b * N_ + m0 + r) * 32))[c];
        }
#pragma unroll
        for (int i = 0; i < 2; i++) {
            int idx = t + i * 256;             // Ss: 512 float4
            int r = idx >> 2, c = idx & 3;
            ((float4*)&Ss[r][0])[c] = ((const float4*)(state + ((size_t)b * N_ + m0 + r) * 16))[c];
        }
        __syncthreads();
#pragma unroll 4
        for (int mm = 0; mm < TM_; mm++) {
            const ulonglong2* kp = (const ulonglong2*)&Ks[mm][head * 8];
            ulonglong2 ka = kp[0], kb = kp[1];
            const ulonglong2* vp = (const ulonglong2*)&Ss[mm][0];
            ulonglong2 va = vp[0], vb = vp[1], vc = vp[2], vd = vp[3];
#pragma unroll
            for (int r = 0; r < 2; r++) {
                ull acc;
                FMA2(acc, q[r][0], ka.x, 0ULL);
                FMA2(acc, q[r][1], ka.y, acc);
                FMA2(acc, q[r][2], kb.x, acc);
                FMA2(acc, q[r][3], kb.y, acc);
                float lo, hi; unpack2(acc, lo, hi);
                float s = fminf(lo + hi, 60.f);
                float p = __expf(s);
                if (r == 0) l0 += p; else l1 += p;
                ull pp = pack2(p, p);
                FMA2(o[r][0], pp, va.x, o[r][0]);
                FMA2(o[r][1], pp, va.y, o[r][1]);
                FMA2(o[r][2], pp, vb.x, o[r][2]);
                FMA2(o[r][3], pp, vb.y, o[r][3]);
                FMA2(o[r][4], pp, vc.x, o[r][4]);
                FMA2(o[r][5], pp, vc.y, o[r][5]);
                FMA2(o[r][6], pp, vd.x, o[r][6]);
                FMA2(o[r][7], pp, vd.y, o[r][7]);
            }
        }
    }

    float gain = 0.25f * v_gains[0];
    float wacc[16];
#pragma unroll
    for (int d = 0; d < 16; d++) wacc[d] = 0.f;
#pragma unroll
    for (int r = 0; r < 2; r++) {
        float inv = 1.f / (r == 0 ? l0 : l1);
        float ov[16];
#pragma unroll
        for (int j = 0; j < 8; j++) unpack2(o[r][j], ov[2*j], ov[2*j+1]);
#pragma unroll
        for (int d = 0; d < 16; d++) {
            float v = ov[d] * inv;
            v += __shfl_xor_sync(0xffffffffu, v, 1);
            v += __shfl_xor_sync(0xffffffffu, v, 2);
            v *= gain;
            ov[d] = v;
            wacc[d] += v;
        }
        if (head == 0) {
            float4* ap = (float4*)(g_att + ((size_t)b * N_ + n0 + r) * 16);
#pragma unroll
            for (int i = 0; i < 4; i++)
                ap[i] = make_float4(ov[4*i], ov[4*i+1], ov[4*i+2], ov[4*i+3]);
        }
    }
#pragma unroll
    for (int d = 0; d < 16; d++) {
        float v = wacc[d];
        v += __shfl_xor_sync(0xffffffffu, v, 4);
        v += __shfl_xor_sync(0xffffffffu, v, 8);
        v += __shfl_xor_sync(0xffffffffu, v, 16);
        wacc[d] = v;
    }
    if ((t & 31) == 0) {
#pragma unroll
        for (int d = 0; d < 16; d++) sW[t >> 5][d] = wacc[d];
    }
    __syncthreads();
    if (t < 16) {
        float s = 0.f;
#pragma unroll
        for (int w = 0; w < 8; w++) s += sW[w][t];
        atomicAdd(&g_wsumAcc[b * 16 + t], s);
    }
}

// ---------------- kernel 3: candidates + fim partials ----------------
__global__ __launch_bounds__(256) void cand_kernel(const float* __restrict__ W_act,
                            const float* __restrict__ b_act) {
    int b = blockIdx.z, k = blockIdx.y, ch = blockIdx.x;
    __shared__ float W[16][16];
    __shared__ float bias[16];
    int t = threadIdx.x;
    W[t >> 4][t & 15] = W_act[(k * 16 + (t >> 4)) * 16 + (t & 15)];
    if (t < 16) bias[t] = b_act[k * 16 + t] + g_hypf[(b * K_ + k) * 16 + t];
    __syncthreads();
    int n = ch * 256 + t;
    float a[16];
    const float4* ap = (const float4*)(g_att + ((size_t)b * N_ + n) * 16);
#pragma unroll
    for (int i = 0; i < 4; i++) { float4 v = ap[i]; a[4*i]=v.x; a[4*i+1]=v.y; a[4*i+2]=v.z; a[4*i+3]=v.w; }
    ull ad[16];
#pragma unroll
    for (int d = 0; d < 16; d++) ad[d] = pack2(a[d], a[d]);
    float c[16], ss = 0.f;
#pragma unroll
    for (int e2 = 0; e2 < 8; e2++) {
        ull acc = ((const ull*)bias)[e2];
#pragma unroll
        for (int d = 0; d < 16; d++) FMA2(acc, ad[d], ((const ull*)&W[d][0])[e2], acc);
        float v0, v1; unpack2(acc, v0, v1);
        v0 = fast_tanh(v0); v1 = fast_tanh(v1);
        c[2*e2] = v0; c[2*e2+1] = v1;
        ss = fmaf(v0, v0, fmaf(v1, v1, ss));
    }
    float4* cp = (float4*)(g_cand + (((size_t)(b * K_ + k)) * N_ + n) * 16);
#pragma unroll
    for (int i = 0; i < 4; i++) cp[i] = make_float4(c[4*i], c[4*i+1], c[4*i+2], c[4*i+3]);
    ss *= (1.f / 16.f);
#pragma unroll
    for (int off = 16; off > 0; off >>= 1) ss += __shfl_xor_sync(0xffffffffu, ss, off);
    __shared__ float wsums[8];
    if ((t & 31) == 0) wsums[t >> 5] = ss;
    __syncthreads();
    if (t == 0) {
        float tot = 0.f;
#pragma unroll
        for (int i = 0; i < 8; i++) tot += wsums[i];
        atomicAdd(&g_fimraw[b * K_ + k], tot);
    }
}

// ---------------- kernel 4: fused small-math + weighted select + gates + norm ----------------
__global__ __launch_bounds__(256) void final_kernel(const float* __restrict__ state,
                            const float* __restrict__ hyp, const float* __restrict__ R_accum,
                            const float* __restrict__ W_ws, const float* __restrict__ b_ws,
                            const float* __restrict__ W_s1, const float* __restrict__ b_s1,
                            const float* __restrict__ W_s2, const float* __restrict__ b_s2,
                            const float* __restrict__ W_lift, const float* __restrict__ b_lift,
                            const float* __restrict__ rotors,
                            const float* __restrict__ Wg1, const float* __restrict__ bg1,
                            const float* __restrict__ Wg2, const float* __restrict__ bg2,
                            const float* __restrict__ Wc1, const float* __restrict__ bc1,
                            const float* __restrict__ Wc2, const float* __restrict__ bc2,
                            const float* __restrict__ norm_scale,
                            float* __restrict__ out_ns, float* __restrict__ out_newhyp,
                            float* __restrict__ out_R, float* __restrict__ out_fim,
                            float* __restrict__ out_w, float* __restrict__ out_gate) {
    int b = blockIdx.y;
    int bx = blockIdx.x;
    int t = threadIdx.x;
    int n = bx * 256 + t;

    __shared__ float sWg1[32][64];
    __shared__ float sWg2[64][16];
    __shared__ float sbg1[64], sbg2[16], sWc1[2][16], sbc1[16], sWc2[16], sns[16];
    __shared__ float sW1[640], sW2[320];
    __shared__ float sC[256];
    __shared__ float s_nh[8][4], s_logit[8], s_fim[8];
    __shared__ float s_w[8], s_agg[4], s_mod[16];
    __shared__ float s_Rt[16], s_Racc[16], s_Rn[16];
    __shared__ float sbc2, s_g0;

    // ---- stage weights ----
    for (int i = t; i < 2048; i += 256) sWg1[i >> 6][i & 63] = Wg1[i];
    for (int i = t; i < 1024; i += 256) sWg2[i >> 4][i & 15] = Wg2[i];
    for (int i = t; i < 640; i += 256) sW1[i] = W_s1[i];
    for (int i = t; i < 320; i += 256) sW2[i] = W_s2[i];
    sC[t] = cayley_sign(t >> 4, t & 15);
    if (t < 64) sbg1[t] = bg1[t];
    if (t < 16) { sbg2[t] = bg2[t]; sbc1[t] = bc1[t]; sWc2[t] = Wc2[t]; sns[t] = norm_scale[t]; }
    if (t < 32) sWc1[t >> 4][t & 15] = Wc1[t];
    if (t == 0) sbc2 = bc2[0];
    __syncthreads();

    // ---- per-batch tiny math (first warp; redundant per block) ----
    const float invN = 1.f / (float)N_;
    if (t < 32) {
        int p = t >> 2;      // k index 0..7
        int q = t & 3;
        float fim = g_fimraw[b * 8 + p] * invN;
        float feat[10];
#pragma unroll
        for (int c = 0; c < 4; c++) feat[c] = hyp[(b * 8 + p) * 4 + c];
#pragma unroll
        for (int c = 0; c < 4; c++) {
            float v = b_ws[c];
#pragma unroll
            for (int d = 0; d < 16; d++)
                v = fmaf(g_wsumAcc[b * 16 + d] * invN, W_ws[d * 4 + c], v);
            feat[4 + c] = v;
        }
        feat[8] = fim; feat[9] = fim;
        float sp[5] = {0.f, 0.f, 0.f, 0.f, 0.f};
        for (int j = q; j < 64; j += 4) {
            float h = b_s1[j];
#pragma unroll
            for (int i = 0; i < 10; i++) h = fmaf(feat[i], sW1[i * 64 + j], h);
            h = fmaxf(h, 0.f);
#pragma unroll
            for (int c = 0; c < 5; c++) sp[c] = fmaf(h, sW2[j * 5 + c], sp[c]);
        }
#pragma unroll
        for (int c = 0; c < 5; c++) {
            sp[c] += __shfl_xor_sync(0xffffffffu, sp[c], 1);
            sp[c] += __shfl_xor_sync(0xffffffffu, sp[c], 2);
        }
        if (q == 0) {
            s_fim[p] = fim;
#pragma unroll
            for (int c = 0; c < 4; c++) s_nh[p][c] = feat[c] + sp[c] + b_s2[c];
            s_logit[p] = sp[4] + b_s2[4];
        }
        __syncwarp();
        if (t == 0) {
            float mx = -1e30f;
#pragma unroll
            for (int k = 0; k < 8; k++) mx = fmaxf(mx, s_logit[k]);
            float e[8], se = 0.f;
#pragma unroll
            for (int k = 0; k < 8; k++) { e[k] = __expf(s_logit[k] - mx); se += e[k]; }
            float inv = 1.f / se;
            float agg[4] = {0.f, 0.f, 0.f, 0.f};
#pragma unroll
            for (int k = 0; k < 8; k++) {
                float w = e[k] * inv;
                s_w[k] = w;
#pragma unroll
                for (int c = 0; c < 4; c++) agg[c] = fmaf(w, s_nh[k][c], agg[c]);
            }
#pragma unroll
            for (int c = 0; c < 4; c++) s_agg[c] = agg[c];
        }
        __syncwarp();
        if (t < 16) {
            float v = b_lift[t];
#pragma unroll
            for (int c = 0; c < 4; c++) v = fmaf(s_agg[c], W_lift[c * 16 + t], v);
            s_mod[t] = 1.f + tanhf(v);
        }
    }
    __syncthreads();

    // ---- block x==0 writes the small outputs + rotor for this batch ----
    if (bx == 0) {
        if (t < 8) { out_fim[b * 8 + t] = s_fim[t]; out_w[b * 8 + t] = s_w[t]; }
        if (t < 32) out_newhyp[b * 32 + t] = s_nh[t >> 2][t & 3];
        if (t < 16) {
            float v = 0.f;
#pragma unroll
            for (int k = 0; k < 8; k++) v = fmaf(s_w[k], rotors[k * 16 + t], v);
            s_Rt[t] = v;
            s_Racc[t] = R_accum[b * 16 + t];
        }
    }
    __syncthreads();
    if (bx == 0) {
        if (t < 16) {
            float v = 0.f;
#pragma unroll
            for (int a = 0; a < 16; a++) {
                int bb = a ^ t;
                v = fmaf(sC[a * 16 + bb] * s_Rt[a], s_Racc[bb], v);
            }
            s_Rn[t] = v;
        }
    }
    __syncthreads();
    if (bx == 0) {
        if (t == 0) {
            float g0 = 0.f;
#pragma unroll
            for (int a = 0; a < 16; a++)
                g0 += sC[a * 16 + a] * s_Rn[a] * s_Rn[a] * rev_sign(a);
            s_g0 = rsqrtf(fmaxf(fabsf(g0), 1e-6f));
        }
    }
    __syncthreads();
    if (bx == 0 && t < 16) out_R[b * 16 + t] = s_Rn[t] * s_g0;

    // ---- main per-cell work ----
    float in[32];
    const float4* sp = (const float4*)(state + ((size_t)b * N_ + n) * 16);
#pragma unroll
    for (int i = 0; i < 4; i++) { float4 v = sp[i]; in[4*i]=v.x; in[4*i+1]=v.y; in[4*i+2]=v.z; in[4*i+3]=v.w; }

    float ns_[16];
#pragma unroll
    for (int e = 0; e < 16; e++) ns_[e] = 0.f;
#pragma unroll
    for (int k = 0; k < 8; k++) {
        const float4* cp = (const float4*)(g_cand + (((size_t)(b * K_ + k)) * N_ + n) * 16);
        float wk = s_w[k];
#pragma unroll
        for (int i = 0; i < 4; i++) {
            float4 v = cp[i];
            ns_[4*i]   = fmaf(wk, v.x, ns_[4*i]);
            ns_[4*i+1] = fmaf(wk, v.y, ns_[4*i+1]);
            ns_[4*i+2] = fmaf(wk, v.z, ns_[4*i+2]);
            ns_[4*i+3] = fmaf(wk, v.w, ns_[4*i+3]);
        }
    }
#pragma unroll
    for (int e = 0; e < 16; e++) { ns_[e] *= s_mod[e]; in[16 + e] = ns_[e]; }

    ull accE[8];
#pragma unroll
    for (int e2 = 0; e2 < 8; e2++) accE[e2] = ((const ull*)sbg2)[e2];
#pragma unroll
    for (int half = 0; half < 2; half++) {
        ull accH[16];
#pragma unroll
        for (int j2 = 0; j2 < 16; j2++) accH[j2] = ((const ull*)sbg1)[half * 16 + j2];
#pragma unroll
        for (int i = 0; i < 32; i++) {
            ull ind = pack2(in[i], in[i]);
            const ull* wrow = (const ull*)&sWg1[i][half * 32];
#pragma unroll
            for (int j2 = 0; j2 < 16; j2++) FMA2(accH[j2], ind, wrow[j2], accH[j2]);
        }
#pragma unroll
        for (int j2 = 0; j2 < 16; j2++) {
            float h0, h1; unpack2(accH[j2], h0, h1);
            h0 = fmaxf(h0, 0.f); h1 = fmaxf(h1, 0.f);
            int j = half * 32 + j2 * 2;
            ull hd0 = pack2(h0, h0), hd1 = pack2(h1, h1);
            const ull* w0 = (const ull*)&sWg2[j][0];
            const ull* w1 = (const ull*)&sWg2[j + 1][0];
#pragma unroll
            for (int e2 = 0; e2 < 8; e2++) {
                FMA2(accE[e2], hd0, w0[e2], accE[e2]);
                FMA2(accE[e2], hd1, w1[e2], accE[e2]);
            }
        }
    }
    float gate[16];
#pragma unroll
    for (int e2 = 0; e2 < 8; e2++) {
        float a0, a1; unpack2(accE[e2], a0, a1);
        gate[2*e2]   = 1.f / (1.f + __expf(-a0));
        gate[2*e2+1] = 1.f / (1.f + __expf(-a1));
    }

    float cg = sbc2;
#pragma unroll
    for (int j = 0; j < 16; j++) {
        float h = fmaf(in[0], sWc1[0][j], fmaf(ns_[0], sWc1[1][j], sbc1[j]));
        h = fmaxf(h, 0.f);
        cg = fmaf(h, sWc2[j], cg);
    }
    cg = 1.f / (1.f + __expf(-cg));

    float val[16];
    val[0] = cg * ns_[0] + (1.f - cg) * in[0];
#pragma unroll
    for (int d = 1; d < 16; d++) val[d] = gate[d] * ns_[d] + (1.f - gate[d]) * in[d];

    float ms = 0.f;
#pragma unroll
    for (int d = 0; d < 16; d++) ms = fmaf(val[d], val[d], ms);
    float r = rsqrtf(ms * (1.f / 16.f) + 1e-6f);

    float4* no = (float4*)(out_ns + ((size_t)b * N_ + n) * 16);
    float4* go = (float4*)(out_gate + ((size_t)b * N_ + n) * 16);
#pragma unroll
    for (int i = 0; i < 4; i++) {
        no[i] = make_float4(val[4*i] * sns[4*i] * r, val[4*i+1] * sns[4*i+1] * r,
                            val[4*i+2] * sns[4*i+2] * r, val[4*i+3] * sns[4*i+3] * r);
        go[i] = make_float4(gate[4*i], gate[4*i+1], gate[4*i+2], gate[4*i+3]);
    }
}

// ---------------- launch ----------------
extern "C" void kernel_launch(void* const* d_in, const int* in_sizes, int n_in,
                              void* d_out, int out_size) {
    const float* state   = (const float*)d_in[0];
    const float* hyp     = (const float*)d_in[1];
    const float* R_accum = (const float*)d_in[2];
    const float* Wq = (const float*)d_in[4];
    const float* bq = (const float*)d_in[5];
    const float* Wk = (const float*)d_in[6];
    const float* bk = (const float*)d_in[7];
    const float* v_gains = (const float*)d_in[8];
    const float* W_act = (const float*)d_in[9];
    const float* b_act = (const float*)d_in[10];
    const float* W_hyp = (const float*)d_in[11];
    const float* b_hyp = (const float*)d_in[12];
    const float* W_ws = (const float*)d_in[13];
    const float* b_ws = (const float*)d_in[14];
    const float* W_s1 = (const float*)d_in[15];
    const float* b_s1 = (const float*)d_in[16];
    const float* W_s2 = (const float*)d_in[17];
    const float* b_s2 = (const float*)d_in[18];
    const float* W_lift = (const float*)d_in[19];
    const float* b_lift = (const float*)d_in[20];
    const float* Wg1 = (const float*)d_in[21];
    const float* bg1 = (const float*)d_in[22];
    const float* Wg2 = (const float*)d_in[23];
    const float* bg2 = (const float*)d_in[24];
    const float* Wc1 = (const float*)d_in[25];
    const float* bc1 = (const float*)d_in[26];
    const float* Wc2 = (const float*)d_in[27];
    const float* bc2 = (const float*)d_in[28];
    const float* norm_scale = (const float*)d_in[29];
    const float* rotors = (const float*)d_in[30];

    float* out = (float*)d_out;
    float* out_ns     = out;
    float* out_newhyp = out + (size_t)B_ * N_ * D_;
    float* out_R      = out_newhyp + B_ * K_ * 4;
    float* out_fim    = out_R + B_ * 16;
    float* out_w      = out_fim + B_ * K_;
    float* out_gate   = out_w + B_ * K_;

    proj_kernel<<<(B_ * N_) / 128, 128>>>(state, Wq, bq, Wk, bk, hyp, W_hyp, b_hyp);
    attn_kernel<<<dim3(N_ / 128, B_), 256>>>(state, v_gains);
    cand_kernel<<<dim3(N_ / 256, K_, B_), 256>>>(W_act, b_act);
    final_kernel<<<dim3(N_ / 256, B_), 256>>>(state, hyp, R_accum, W_ws, b_ws,
                                              W_s1, b_s1, W_s2, b_s2, W_lift, b_lift, rotors,
                                              Wg1, bg1, Wg2, bg2, Wc1, bc1, Wc2, bc2, norm_scale,
                                              out_ns, out_newhyp, out_R, out_fim, out_w, out_gate);
}